// round 14
// baseline (speedup 1.0000x reference)
#include <cuda_runtime.h>
#include <cuda_fp16.h>
#include <cstdint>

#define D        128
#define N1       81920
#define BATCH    8192
#define KNB      10
#define NTHREADS 256
#define KPAD     136        // padded k-stride in fp16 elems
#define ROWB     (KPAD * 2) // 272 bytes per row
#define BTILE    34816      // one B phase: 128 rows * ROWB

// ---------------- device-global scratch (allocation-free rule) ----------------
__device__ float g_h1[(size_t)N1 * D];                 // layer-1 embeddings

// ---------------- PTX helpers ----------------
__device__ __forceinline__ uint32_t smem_u32(const void* p) {
    uint32_t a;
    asm("{ .reg .u64 t; cvta.to.shared.u64 t, %1; cvt.u32.u64 %0, t; }"
        : "=r"(a) : "l"(p));
    return a;
}
#define LDSM4(r, addr)                                                       \
    asm volatile("ldmatrix.sync.aligned.m8n8.x4.shared.b16 {%0,%1,%2,%3}, [%4];" \
                 : "=r"((r)[0]), "=r"((r)[1]), "=r"((r)[2]), "=r"((r)[3])    \
                 : "r"(addr))
#define MMAF16(c, a, b0, b1)                                                 \
    asm volatile("mma.sync.aligned.m16n8k16.row.col.f32.f16.f16.f32 "        \
                 "{%0,%1,%2,%3}, {%4,%5,%6,%7}, {%8,%9}, {%0,%1,%2,%3};"     \
                 : "+f"((c)[0]), "+f"((c)[1]), "+f"((c)[2]), "+f"((c)[3])    \
                 : "r"((a)[0]), "r"((a)[1]), "r"((a)[2]), "r"((a)[3]),       \
                   "r"(b0), "r"(b1))

__device__ __forceinline__ uint32_t pack_h2(float a, float b) {
    __half2 h = __floats2half2_rn(a, b);
    return *(uint32_t*)&h;
}
// convert float4 -> 4 fp16, one 8-B store
__device__ __forceinline__ void store_f16x4(char* p, float4 v) {
    uint2 hv;
    hv.x = pack_h2(v.x, v.y);
    hv.y = pack_h2(v.z, v.w);
    *(uint2*)p = hv;
}

// one K=128 phase, single-product fp16 GEMM: acc += A * B
template <int NQ>
__device__ __forceinline__ void mma_phase(uint32_t aB, uint32_t bB,
                                          int lane, float acc[2][2 * NQ][4]) {
    const uint32_t pa = (uint32_t)((lane & 15) * ROWB + (lane >> 4) * 16);
    const uint32_t pb = (uint32_t)(((lane & 7) + ((lane >> 4) << 3)) * ROWB +
                                   ((lane >> 3) & 1) * 16);
    #pragma unroll
    for (int ks = 0; ks < 8; ks++) {
        const uint32_t ko = ks * 32;
        uint32_t a[2][4];
        #pragma unroll
        for (int mt = 0; mt < 2; mt++)
            LDSM4(a[mt], aB + pa + mt * 16 * ROWB + ko);
        #pragma unroll
        for (int nq = 0; nq < NQ; nq++) {
            uint32_t b[4];
            LDSM4(b, bB + pb + nq * 16 * ROWB + ko);
            #pragma unroll
            for (int mt = 0; mt < 2; mt++) {
                MMAF16(acc[mt][nq * 2 + 0], a[mt], b[0], b[1]);
                MMAF16(acc[mt][nq * 2 + 1], a[mt], b[2], b[3]);
            }
        }
    }
}

// ---------------- fused SAGE layer, single-product fp16 -----------------------
// TM_ rows/block; warp grid WM_ x WN_ (8 warps), warp tile 32 x (128/WN_).
// smem: A0 [TM][KPAD] fp16, A1 [TM][KPAD] fp16, B0+B1 [128][KPAD] fp16 each.
// One __syncthreads total: stage B0+B1 and gather, sync, then both MMA phases.
template <int LAYER, int TM_, int WM_, int WN_>
__global__ __launch_bounds__(NTHREADS, 2)
void sage_mma_kernel(const float* __restrict__ feats_in,
                     const float* __restrict__ Wg,
                     const int*   __restrict__ self_idx,
                     const int*   __restrict__ neigh_idx,
                     float*       __restrict__ out_ext) {
    constexpr int NW  = 128 / WN_;          // cols per warp tile
    constexpr int NQ  = NW / 16;
    constexpr int RPW = TM_ / 8;            // gather rows per warp
    constexpr int OFF_A0 = 0;
    constexpr int OFF_A1 = TM_ * ROWB;
    constexpr int OFF_B0 = 2 * TM_ * ROWB;
    constexpr int OFF_B1 = OFF_B0 + BTILE;

    extern __shared__ char smem[];
    const uint32_t sb = smem_u32(smem);
    const int t = threadIdx.x, lane = t & 31, wid = t >> 5;

    const float* feats = (LAYER == 1) ? feats_in : g_h1;
    float*       out   = (LAYER == 1) ? g_h1 : out_ext;

    // ---- stage both B phases upfront: W[:, 0:128] and W[:, 128:256] ----
    {
        #pragma unroll
        for (int it = 0; it < 16; it++) {
            const int row = wid + it * 8;
            float4 v0 = __ldg((const float4*)(Wg + row * 256) + lane);
            float4 v1 = __ldg((const float4*)(Wg + row * 256 + 128) + lane);
            store_f16x4(smem + OFF_B0 + row * ROWB + lane * 8, v0);
            store_f16x4(smem + OFF_B1 + row * ROWB + lane * 8, v1);
        }
    }

    // ---- gather: RPW rows/warp; self -> A0, mean-agg -> A1 (fp16) ----
    {
        #pragma unroll 2
        for (int rr = 0; rr < RPW; rr++) {
            const int r    = wid * RPW + rr;
            const int row  = blockIdx.x * TM_ + r;
            const int nsel = __ldg(&self_idx[row]);
            float4 s = __ldg((const float4*)&feats[(size_t)nsel * D] + lane);
            float4 a = make_float4(0.f, 0.f, 0.f, 0.f);
            #pragma unroll
            for (int k = 0; k < KNB; k++) {
                const int nk = __ldg(&neigh_idx[row * KNB + k]);
                float4 f = __ldg((const float4*)&feats[(size_t)nk * D] + lane);
                a.x += f.x; a.y += f.y; a.z += f.z; a.w += f.w;
            }
            const float inv = 1.0f / (float)KNB;
            a.x *= inv; a.y *= inv; a.z *= inv; a.w *= inv;
            const int so = r * ROWB + lane * 8;
            store_f16x4(smem + OFF_A0 + so, s);
            store_f16x4(smem + OFF_A1 + so, a);
        }
    }
    __syncthreads();

    // ---- warp tiling ----
    const int wm = wid % WM_, wn = wid / WM_;
    const uint32_t aoff = (uint32_t)(wm * 32 * ROWB);
    const uint32_t boff = (uint32_t)(wn * NW * ROWB);

    float acc[2][2 * NQ][4];
    #pragma unroll
    for (int mt = 0; mt < 2; mt++)
        #pragma unroll
        for (int nt = 0; nt < 2 * NQ; nt++)
            #pragma unroll
            for (int c = 0; c < 4; c++) acc[mt][nt][c] = 0.0f;

    // ---- phase 0: self x W[:, 0:128];  phase 1: agg x W[:, 128:256] ----
    mma_phase<NQ>(sb + OFF_A0 + aoff, sb + OFF_B0 + boff, lane, acc);
    mma_phase<NQ>(sb + OFF_A1 + aoff, sb + OFF_B1 + boff, lane, acc);

    // ---- epilogue: ReLU + float2 stores ----
    const int rb = blockIdx.x * TM_ + wm * 32 + (lane >> 2);
    const int cb = wn * NW + (lane & 3) * 2;
    #pragma unroll
    for (int mt = 0; mt < 2; mt++)
        #pragma unroll
        for (int nt = 0; nt < 2 * NQ; nt++) {
            const int row = rb + mt * 16;
            const int col = cb + nt * 8;
            float2 v0 = make_float2(fmaxf(acc[mt][nt][0], 0.f),
                                    fmaxf(acc[mt][nt][1], 0.f));
            float2 v1 = make_float2(fmaxf(acc[mt][nt][2], 0.f),
                                    fmaxf(acc[mt][nt][3], 0.f));
            *(float2*)&out[(size_t)row * D + col]       = v0;
            *(float2*)&out[(size_t)(row + 8) * D + col] = v1;
        }
}

// ---------------- launch ----------------
extern "C" void kernel_launch(void* const* d_in, const int* in_sizes, int n_in,
                              void* d_out, int out_size) {
    const float* raw_features = (const float*)d_in[0];
    const float* W1           = (const float*)d_in[1];
    const float* W2           = (const float*)d_in[2];
    const int*   layer1_nodes = (const int*)d_in[3];
    const int*   neigh0_idx   = (const int*)d_in[4];
    const int*   map_batch    = (const int*)d_in[5];
    const int*   neigh1_idx   = (const int*)d_in[6];
    float*       out          = (float*)d_out;

    // layer 1: TM=64, warps 2m x 4n (tile 32x32): smem 104448 -> 2 CTAs/SM
    constexpr int SMEM1 = 2 * 64 * ROWB + 2 * BTILE;   // 104448
    // layer 2: TM=32, warps 1m x 8n (tile 32x16): smem 87040
    constexpr int SMEM2 = 2 * 32 * ROWB + 2 * BTILE;   // 87040

    cudaFuncSetAttribute((const void*)sage_mma_kernel<1, 64, 2, 4>,
                         cudaFuncAttributeMaxDynamicSharedMemorySize, SMEM1);
    cudaFuncSetAttribute((const void*)sage_mma_kernel<2, 32, 1, 8>,
                         cudaFuncAttributeMaxDynamicSharedMemorySize, SMEM2);

    sage_mma_kernel<1, 64, 2, 4><<<N1 / 64, NTHREADS, SMEM1>>>(
        raw_features, W1, layer1_nodes, neigh0_idx, nullptr);
    sage_mma_kernel<2, 32, 1, 8><<<BATCH / 32, NTHREADS, SMEM2>>>(
        nullptr, W2, map_batch, neigh1_idx, out);
}

// round 17
// speedup vs baseline: 1.3545x; 1.3545x over previous
#include <cuda_runtime.h>
#include <cuda_fp16.h>
#include <cstdint>

#define D        128
#define N1       81920
#define BATCH    8192
#define KNB      10
#define NTHREADS 256
#define KPAD     136        // padded k-stride in fp16 elems
#define ROWB     (KPAD * 2) // 272 bytes per row
#define BTILE    34816      // one B phase: 128 rows * ROWB

// ---------------- device-global scratch (allocation-free rule) ----------------
__device__ float g_h1[(size_t)N1 * D];                 // layer-1 embeddings

// ---------------- PTX helpers ----------------
__device__ __forceinline__ uint32_t smem_u32(const void* p) {
    uint32_t a;
    asm("{ .reg .u64 t; cvta.to.shared.u64 t, %1; cvt.u32.u64 %0, t; }"
        : "=r"(a) : "l"(p));
    return a;
}
#define LDSM4(r, addr)                                                       \
    asm volatile("ldmatrix.sync.aligned.m8n8.x4.shared.b16 {%0,%1,%2,%3}, [%4];" \
                 : "=r"((r)[0]), "=r"((r)[1]), "=r"((r)[2]), "=r"((r)[3])    \
                 : "r"(addr))
#define MMAF16(c, a, b0, b1)                                                 \
    asm volatile("mma.sync.aligned.m16n8k16.row.col.f32.f16.f16.f32 "        \
                 "{%0,%1,%2,%3}, {%4,%5,%6,%7}, {%8,%9}, {%0,%1,%2,%3};"     \
                 : "+f"((c)[0]), "+f"((c)[1]), "+f"((c)[2]), "+f"((c)[3])    \
                 : "r"((a)[0]), "r"((a)[1]), "r"((a)[2]), "r"((a)[3]),       \
                   "r"(b0), "r"(b1))

__device__ __forceinline__ uint32_t pack_h2(float a, float b) {
    __half2 h = __floats2half2_rn(a, b);
    return *(uint32_t*)&h;
}
// convert float4 -> 4 fp16, one 8-B store
__device__ __forceinline__ void store_f16x4(char* p, float4 v) {
    uint2 hv;
    hv.x = pack_h2(v.x, v.y);
    hv.y = pack_h2(v.z, v.w);
    *(uint2*)p = hv;
}

// one K=128 phase, single-product fp16 GEMM: acc += A * B
template <int NQ>
__device__ __forceinline__ void mma_phase(uint32_t aB, uint32_t bB,
                                          int lane, float acc[2][2 * NQ][4]) {
    const uint32_t pa = (uint32_t)((lane & 15) * ROWB + (lane >> 4) * 16);
    const uint32_t pb = (uint32_t)(((lane & 7) + ((lane >> 4) << 3)) * ROWB +
                                   ((lane >> 3) & 1) * 16);
    #pragma unroll
    for (int ks = 0; ks < 8; ks++) {
        const uint32_t ko = ks * 32;
        uint32_t a[2][4];
        #pragma unroll
        for (int mt = 0; mt < 2; mt++)
            LDSM4(a[mt], aB + pa + mt * 16 * ROWB + ko);
        #pragma unroll
        for (int nq = 0; nq < NQ; nq++) {
            uint32_t b[4];
            LDSM4(b, bB + pb + nq * 16 * ROWB + ko);
            #pragma unroll
            for (int mt = 0; mt < 2; mt++) {
                MMAF16(acc[mt][nq * 2 + 0], a[mt], b[0], b[1]);
                MMAF16(acc[mt][nq * 2 + 1], a[mt], b[2], b[3]);
            }
        }
    }
}

// stage one K=128 phase of W into smem as fp16 [128 n][KPAD]
__device__ __forceinline__ void stage_B(const float* __restrict__ Wg, int phase,
                                        char* bsm, int wid, int lane) {
    #pragma unroll
    for (int it = 0; it < 16; it++) {
        const int row = wid + it * 8;
        float4 v = __ldg((const float4*)(Wg + row * 256 + phase * 128) + lane);
        store_f16x4(bsm + row * ROWB + lane * 8, v);
    }
}

// ---------------- fused SAGE layer, single-product fp16, 3 CTAs/SM -----------
// R13 structure: stage B0 | gather | sync | MMA0 | sync | stage B1 | sync | MMA1
template <int LAYER, int TM_, int WM_, int WN_>
__global__ __launch_bounds__(NTHREADS, 3)
void sage_mma_kernel(const float* __restrict__ feats_in,
                     const float* __restrict__ Wg,
                     const int*   __restrict__ self_idx,
                     const int*   __restrict__ neigh_idx,
                     float*       __restrict__ out_ext) {
    constexpr int NW  = 128 / WN_;          // cols per warp tile
    constexpr int NQ  = NW / 16;
    constexpr int RPW = TM_ / 8;            // gather rows per warp
    constexpr int OFF_A0 = 0;
    constexpr int OFF_A1 = TM_ * ROWB;
    constexpr int OFF_B  = 2 * TM_ * ROWB;  // single B phase buffer

    extern __shared__ char smem[];
    const uint32_t sb = smem_u32(smem);
    const int t = threadIdx.x, lane = t & 31, wid = t >> 5;

    const float* feats = (LAYER == 1) ? feats_in : g_h1;
    float*       out   = (LAYER == 1) ? g_h1 : out_ext;

    // ---- stage B phase 0 ----
    stage_B(Wg, 0, smem + OFF_B, wid, lane);

    // ---- gather: RPW rows/warp; self -> A0, mean-agg -> A1 (fp16) ----
    {
        #pragma unroll 2
        for (int rr = 0; rr < RPW; rr++) {
            const int r    = wid * RPW + rr;
            const int row  = blockIdx.x * TM_ + r;
            const int nsel = __ldg(&self_idx[row]);
            float4 s = __ldg((const float4*)&feats[(size_t)nsel * D] + lane);
            float4 a = make_float4(0.f, 0.f, 0.f, 0.f);
            #pragma unroll
            for (int k = 0; k < KNB; k++) {
                const int nk = __ldg(&neigh_idx[row * KNB + k]);
                float4 f = __ldg((const float4*)&feats[(size_t)nk * D] + lane);
                a.x += f.x; a.y += f.y; a.z += f.z; a.w += f.w;
            }
            const float inv = 1.0f / (float)KNB;
            a.x *= inv; a.y *= inv; a.z *= inv; a.w *= inv;
            const int so = r * ROWB + lane * 8;
            store_f16x4(smem + OFF_A0 + so, s);
            store_f16x4(smem + OFF_A1 + so, a);
        }
    }
    __syncthreads();

    // ---- warp tiling ----
    const int wm = wid % WM_, wn = wid / WM_;
    const uint32_t aoff = (uint32_t)(wm * 32 * ROWB);
    const uint32_t boff = (uint32_t)(wn * NW * ROWB);

    float acc[2][2 * NQ][4];
    #pragma unroll
    for (int mt = 0; mt < 2; mt++)
        #pragma unroll
        for (int nt = 0; nt < 2 * NQ; nt++)
            #pragma unroll
            for (int c = 0; c < 4; c++) acc[mt][nt][c] = 0.0f;

    // ---- phase 0: self x W[:, 0:128] ----
    mma_phase<NQ>(sb + OFF_A0 + aoff, sb + OFF_B + boff, lane, acc);

    // ---- restage B for phase 1 ----
    __syncthreads();
    stage_B(Wg, 1, smem + OFF_B, wid, lane);
    __syncthreads();

    // ---- phase 1: agg x W[:, 128:256] ----
    mma_phase<NQ>(sb + OFF_A1 + aoff, sb + OFF_B + boff, lane, acc);

    // ---- epilogue: ReLU + float2 stores ----
    const int rb = blockIdx.x * TM_ + wm * 32 + (lane >> 2);
    const int cb = wn * NW + (lane & 3) * 2;
    #pragma unroll
    for (int mt = 0; mt < 2; mt++)
        #pragma unroll
        for (int nt = 0; nt < 2 * NQ; nt++) {
            const int row = rb + mt * 16;
            const int col = cb + nt * 8;
            float2 v0 = make_float2(fmaxf(acc[mt][nt][0], 0.f),
                                    fmaxf(acc[mt][nt][1], 0.f));
            float2 v1 = make_float2(fmaxf(acc[mt][nt][2], 0.f),
                                    fmaxf(acc[mt][nt][3], 0.f));
            *(float2*)&out[(size_t)row * D + col]       = v0;
            *(float2*)&out[(size_t)(row + 8) * D + col] = v1;
        }
}

// ---------------- launch ----------------
extern "C" void kernel_launch(void* const* d_in, const int* in_sizes, int n_in,
                              void* d_out, int out_size) {
    const float* raw_features = (const float*)d_in[0];
    const float* W1           = (const float*)d_in[1];
    const float* W2           = (const float*)d_in[2];
    const int*   layer1_nodes = (const int*)d_in[3];
    const int*   neigh0_idx   = (const int*)d_in[4];
    const int*   map_batch    = (const int*)d_in[5];
    const int*   neigh1_idx   = (const int*)d_in[6];
    float*       out          = (float*)d_out;

    // layer 1: TM=64, warps 2m x 4n (tile 32x32): smem 69632 -> 3 CTAs/SM
    constexpr int SMEM1 = 2 * 64 * ROWB + BTILE;   // 69632
    // layer 2: TM=32, warps 1m x 8n (tile 32x16): smem 52224 -> 3 CTAs/SM
    constexpr int SMEM2 = 2 * 32 * ROWB + BTILE;   // 52224

    cudaFuncSetAttribute((const void*)sage_mma_kernel<1, 64, 2, 4>,
                         cudaFuncAttributeMaxDynamicSharedMemorySize, SMEM1);
    cudaFuncSetAttribute((const void*)sage_mma_kernel<2, 32, 1, 8>,
                         cudaFuncAttributeMaxDynamicSharedMemorySize, SMEM2);

    sage_mma_kernel<1, 64, 2, 4><<<N1 / 64, NTHREADS, SMEM1>>>(
        raw_features, W1, layer1_nodes, neigh0_idx, nullptr);
    sage_mma_kernel<2, 32, 1, 8><<<BATCH / 32, NTHREADS, SMEM2>>>(
        nullptr, W2, map_batch, neigh1_idx, out);
}